// round 4
// baseline (speedup 1.0000x reference)
#include <cuda_runtime.h>
#include <cstdint>

#define BB  4
#define SS  2048
#define DD  1024
#define HH  16
#define DKK 64
#define NN  (BB*SS)
#define AST 68

// ---- warp-MMA GEMM tiling ----
#define BM   128
#define BN   128
#define BK   16
#define NIT  (DD/BK)            // 64
#define RS   20                 // smem row stride (floats), conflict-free
#define PLANEF (BM*RS)          // 2560 floats (one raw matrix tile)
#define STAGEF (2*PLANEF)       // A + B raw per stage
#define NST  4
#define GEMM_SMEM (NST*STAGEF*4)   // 81920 bytes

// scratch
__device__ float g_wt[3][DD*DD];
__device__ float g_q[NN*DD];    // [B,S,H,DK] == [8192][1024]
__device__ float g_k[NN*DD];
__device__ float g_v[NN*DD];
__device__ float g_c[NN*DD];

__device__ __forceinline__ uint32_t smem_u32(const void* p) {
    uint32_t a;
    asm("{ .reg .u64 t; cvta.to.shared.u64 t, %1; cvt.u32.u64 %0, t; }" : "=r"(a) : "l"(p));
    return a;
}
__device__ __forceinline__ float tf32r(float x) {
    uint32_t u;
    asm("cvt.rna.tf32.f32 %0, %1;" : "=r"(u) : "f"(x));
    return __uint_as_float(u);
}
__device__ __forceinline__ void cpa16(uint32_t s, const void* g) {
    asm volatile("cp.async.cg.shared.global [%0], [%1], 16;" :: "r"(s), "l"(g));
}
__device__ __forceinline__ void cpa_commit() {
    asm volatile("cp.async.commit_group;" ::: "memory");
}
__device__ __forceinline__ void cpa_wait2() {
    asm volatile("cp.async.wait_group 2;" ::: "memory");
}
__device__ __forceinline__ void mma8(float* d, const float* a, const float* b) {
    asm volatile("mma.sync.aligned.m16n8k8.row.col.f32.tf32.tf32.f32 "
        "{%0,%1,%2,%3}, {%4,%5,%6,%7}, {%8,%9}, {%0,%1,%2,%3};"
        : "+f"(d[0]), "+f"(d[1]), "+f"(d[2]), "+f"(d[3])
        : "r"(__float_as_uint(a[0])), "r"(__float_as_uint(a[1])),
          "r"(__float_as_uint(a[2])), "r"(__float_as_uint(a[3])),
          "r"(__float_as_uint(b[0])), "r"(__float_as_uint(b[1])));
}

// ---------------------------------------------------------------------------
// Weight transpose: Wt[h*64+dk][d] = W[h][d][dk]
// ---------------------------------------------------------------------------
__global__ void transpose_w(const float* __restrict__ W, float* __restrict__ Wt) {
    __shared__ float t[32][33];
    const int h  = blockIdx.z;
    const int d0 = blockIdx.y << 5;
    const int k0 = blockIdx.x << 5;
    const int c  = threadIdx.x & 31;
    const int r4 = threadIdx.x >> 5;
    const float* Wh = W + ((size_t)h << 16);
    #pragma unroll
    for (int i = 0; i < 4; i++)
        t[r4 + 8*i][c] = Wh[(size_t)(d0 + r4 + 8*i) * DKK + k0 + c];
    __syncthreads();
    float* o = Wt + (size_t)(h * DKK + k0) * DD + d0;
    #pragma unroll
    for (int i = 0; i < 4; i++)
        o[(size_t)(r4 + 8*i) * DD + c] = t[c][r4 + 8*i];
}

// ---------------------------------------------------------------------------
// tf32x3 warp-MMA GEMM: C[m][n] = sum_k A[m][k]*B[n][k] (+bias[n])
// Raw fp32 tiles staged via 4-deep cp.async; hi/lo split at fragment load.
// 256 threads, BM=128 BN=128 BK=16, warp tile 64x32, 2 CTAs/SM.
// ---------------------------------------------------------------------------
__global__ __launch_bounds__(256, 2)
void gemm_tf32(const float* __restrict__ A, const float* __restrict__ B,
               const float* __restrict__ bias, float* __restrict__ C)
{
    extern __shared__ float sm[];
    const uint32_t smb = smem_u32(sm);
    const int tid  = threadIdx.x;
    const int m0   = blockIdx.y * BM;
    const int n0   = blockIdx.x * BN;
    const int w    = tid >> 5, lane = tid & 31;
    const int grp  = lane >> 2, tig = lane & 3;
    const int m_off = (w >> 2) * 64;
    const int n_off = (w & 3) * 32;

    const int lrow0 = tid >> 2, lc4 = (tid & 3) * 4;
    const int lrow1 = lrow0 + 64;

    float acc[4][4][4];
    #pragma unroll
    for (int t = 0; t < 4; t++)
        #pragma unroll
        for (int u = 0; u < 4; u++)
            #pragma unroll
            for (int q = 0; q < 4; q++) acc[t][u][q] = 0.f;

    // issue loads for chunk k0 into stage slot
    #define ISSUE(k0idx, slot)                                                    \
    {                                                                             \
        const int kk0 = (k0idx) * BK;                                             \
        const uint32_t sa = smb + (uint32_t)(slot) * (STAGEF * 4u);               \
        const uint32_t sbb = sa + PLANEF * 4u;                                    \
        cpa16(sa  + (uint32_t)(lrow0*RS + lc4) * 4u, A + (size_t)(m0 + lrow0)*DD + kk0 + lc4); \
        cpa16(sa  + (uint32_t)(lrow1*RS + lc4) * 4u, A + (size_t)(m0 + lrow1)*DD + kk0 + lc4); \
        cpa16(sbb + (uint32_t)(lrow0*RS + lc4) * 4u, B + (size_t)(n0 + lrow0)*DD + kk0 + lc4); \
        cpa16(sbb + (uint32_t)(lrow1*RS + lc4) * 4u, B + (size_t)(n0 + lrow1)*DD + kk0 + lc4); \
    }

    // prologue: stages 0..2
    ISSUE(0, 0); cpa_commit();
    ISSUE(1, 1); cpa_commit();
    ISSUE(2, 2); cpa_commit();

    for (int c = 0; c < NIT; ++c) {
        cpa_wait2();
        __syncthreads();
        if (c + 3 < NIT) ISSUE(c + 3, (c + 3) & (NST - 1));
        cpa_commit();

        const float* As = sm + (c & (NST - 1)) * STAGEF;
        const float* Bs = As + PLANEF;

        #pragma unroll
        for (int s = 0; s < 2; ++s) {
            const int kk = s * 8;
            float ah[4][4], al[4][4];
            #pragma unroll
            for (int t = 0; t < 4; t++) {
                const int r = m_off + t * 16 + grp;
                const int ci = kk + tig;
                float x0 = As[r*RS + ci];
                float x1 = As[(r+8)*RS + ci];
                float x2 = As[r*RS + ci + 4];
                float x3 = As[(r+8)*RS + ci + 4];
                ah[t][0] = tf32r(x0); al[t][0] = tf32r(x0 - ah[t][0]);
                ah[t][1] = tf32r(x1); al[t][1] = tf32r(x1 - ah[t][1]);
                ah[t][2] = tf32r(x2); al[t][2] = tf32r(x2 - ah[t][2]);
                ah[t][3] = tf32r(x3); al[t][3] = tf32r(x3 - ah[t][3]);
            }
            #pragma unroll
            for (int u = 0; u < 4; u++) {
                const int n = n_off + u * 8 + grp;
                const int ci = kk + tig;
                float y0 = Bs[n*RS + ci];
                float y1 = Bs[n*RS + ci + 4];
                float bh[2], bl[2];
                bh[0] = tf32r(y0); bl[0] = tf32r(y0 - bh[0]);
                bh[1] = tf32r(y1); bl[1] = tf32r(y1 - bh[1]);
                #pragma unroll
                for (int t = 0; t < 4; t++) {
                    mma8(acc[t][u], ah[t], bh);
                    mma8(acc[t][u], ah[t], bl);
                    mma8(acc[t][u], al[t], bh);
                }
            }
        }
    }
    #undef ISSUE

    const bool hasb = (bias != nullptr);
    #pragma unroll
    for (int u = 0; u < 4; u++) {
        const int ncol = n0 + n_off + u * 8 + tig * 2;
        float2 bv = make_float2(0.f, 0.f);
        if (hasb) bv = *reinterpret_cast<const float2*>(bias + ncol);
        #pragma unroll
        for (int t = 0; t < 4; t++) {
            const int r = m0 + m_off + t * 16 + grp;
            *reinterpret_cast<float2*>(C + (size_t)r * DD + ncol) =
                make_float2(acc[t][u][0] + bv.x, acc[t][u][1] + bv.y);
            *reinterpret_cast<float2*>(C + (size_t)(r + 8) * DD + ncol) =
                make_float2(acc[t][u][2] + bv.x, acc[t][u][3] + bv.y);
        }
    }
}

// ---------------------------------------------------------------------------
// Causal flash attention, fp32 FFMA. q/k/v layout [B,S,H,DK] (row stride DD).
// ---------------------------------------------------------------------------
__global__ __launch_bounds__(256)
void attn_kernel(const float* __restrict__ gq, const float* __restrict__ gk,
                 const float* __restrict__ gv, float* __restrict__ gc)
{
    extern __shared__ float smf[];
    float* Qs = smf;
    float* Ks = smf + 64*AST;
    float* Vs = smf + 2*64*AST;
    float* Ps = smf + 3*64*AST;

    const int tid = threadIdx.x;
    const int ty  = tid >> 4, tx = tid & 15;
    const int h   = blockIdx.y, b = blockIdx.z;
    const int st  = gridDim.x - 1 - blockIdx.x;
    const int s0  = st * 64;
    const int r0  = ty * 4, c0 = tx * 4;

    const float* qb = gq + ((size_t)b * SS + s0) * DD + h * DKK;
    const float* kb = gk + (size_t)b * SS * DD + h * DKK;
    const float* vb = gv + (size_t)b * SS * DD + h * DKK;

    #pragma unroll
    for (int u = 0; u < 4; u++) {
        int f = tid + u * 256;
        int row = f >> 4, c4 = f & 15;
        *reinterpret_cast<float4*>(Qs + row*AST + c4*4) =
            *reinterpret_cast<const float4*>(qb + (size_t)row * DD + c4*4);
    }

    float m[4], l[4], o[4][4];
    #pragma unroll
    for (int i = 0; i < 4; i++) {
        m[i] = -1e30f; l[i] = 0.f;
        #pragma unroll
        for (int j = 0; j < 4; j++) o[i][j] = 0.f;
    }

    const int ntiles = st + 1;
    for (int tt = 0; tt < ntiles; ++tt) {
        const int t0 = tt * 64;
        __syncthreads();
        #pragma unroll
        for (int u = 0; u < 4; u++) {
            int f = tid + u * 256;
            int row = f >> 4, c4 = f & 15;
            float4 kv = *reinterpret_cast<const float4*>(kb + (size_t)(t0+row) * DD + c4*4);
            Ks[(c4*4+0)*AST + row] = kv.x;
            Ks[(c4*4+1)*AST + row] = kv.y;
            Ks[(c4*4+2)*AST + row] = kv.z;
            Ks[(c4*4+3)*AST + row] = kv.w;
            *reinterpret_cast<float4*>(Vs + row*AST + c4*4) =
                *reinterpret_cast<const float4*>(vb + (size_t)(t0+row) * DD + c4*4);
        }
        __syncthreads();

        float sv[4][4];
        #pragma unroll
        for (int i = 0; i < 4; i++)
            #pragma unroll
            for (int j = 0; j < 4; j++) sv[i][j] = 0.f;

        #pragma unroll 16
        for (int kk = 0; kk < 64; kk++) {
            float a[4];
            #pragma unroll
            for (int i = 0; i < 4; i++) a[i] = Qs[(r0+i)*AST + kk];
            float4 b4 = *reinterpret_cast<const float4*>(Ks + kk*AST + c0);
            float bv[4] = {b4.x, b4.y, b4.z, b4.w};
            #pragma unroll
            for (int i = 0; i < 4; i++)
                #pragma unroll
                for (int j = 0; j < 4; j++)
                    sv[i][j] = fmaf(a[i], bv[j], sv[i][j]);
        }

        #pragma unroll
        for (int i = 0; i < 4; i++)
            #pragma unroll
            for (int j = 0; j < 4; j++) sv[i][j] *= 8.0f;
        if (t0 == s0) {
            #pragma unroll
            for (int i = 0; i < 4; i++)
                #pragma unroll
                for (int j = 0; j < 4; j++)
                    if (c0 + j > r0 + i) sv[i][j] = -1e30f;
        }

        float mt[4];
        #pragma unroll
        for (int i = 0; i < 4; i++)
            mt[i] = fmaxf(fmaxf(sv[i][0], sv[i][1]), fmaxf(sv[i][2], sv[i][3]));
        #pragma unroll
        for (int off = 8; off; off >>= 1)
            #pragma unroll
            for (int i = 0; i < 4; i++)
                mt[i] = fmaxf(mt[i], __shfl_xor_sync(0xffffffffu, mt[i], off));

        float mn[4], alpha[4];
        #pragma unroll
        for (int i = 0; i < 4; i++) {
            mn[i] = fmaxf(m[i], mt[i]);
            alpha[i] = __expf(m[i] - mn[i]);
            m[i] = mn[i];
        }

        float p[4][4], ls[4];
        #pragma unroll
        for (int i = 0; i < 4; i++) {
            ls[i] = 0.f;
            #pragma unroll
            for (int j = 0; j < 4; j++) {
                p[i][j] = __expf(sv[i][j] - mn[i]);
                ls[i] += p[i][j];
            }
        }
        #pragma unroll
        for (int off = 8; off; off >>= 1)
            #pragma unroll
            for (int i = 0; i < 4; i++)
                ls[i] += __shfl_xor_sync(0xffffffffu, ls[i], off);

        #pragma unroll
        for (int i = 0; i < 4; i++) {
            l[i] = l[i] * alpha[i] + ls[i];
            #pragma unroll
            for (int j = 0; j < 4; j++) o[i][j] *= alpha[i];
        }

        #pragma unroll
        for (int i = 0; i < 4; i++)
            *reinterpret_cast<float4*>(Ps + (r0+i)*AST + c0) =
                make_float4(p[i][0], p[i][1], p[i][2], p[i][3]);
        __syncthreads();

        #pragma unroll 16
        for (int kk = 0; kk < 64; kk++) {
            float a[4];
            #pragma unroll
            for (int i = 0; i < 4; i++) a[i] = Ps[(r0+i)*AST + kk];
            float4 b4 = *reinterpret_cast<const float4*>(Vs + kk*AST + c0);
            float bv[4] = {b4.x, b4.y, b4.z, b4.w};
            #pragma unroll
            for (int i = 0; i < 4; i++)
                #pragma unroll
                for (int j = 0; j < 4; j++)
                    o[i][j] = fmaf(a[i], bv[j], o[i][j]);
        }
    }

    float* outp = gc + ((size_t)b * SS + s0) * DD + h * DKK;
    #pragma unroll
    for (int i = 0; i < 4; i++) {
        float inv = 1.0f / l[i];
        float4 ov = make_float4(o[i][0]*inv, o[i][1]*inv, o[i][2]*inv, o[i][3]*inv);
        *reinterpret_cast<float4*>(outp + (size_t)(r0+i) * DD + c0) = ov;
    }
}

// ---------------------------------------------------------------------------
extern "C" void kernel_launch(void* const* d_in, const int* in_sizes, int n_in,
                              void* d_out, int out_size)
{
    const float* Q  = (const float*)d_in[0];
    const float* K  = (const float*)d_in[1];
    const float* V  = (const float*)d_in[2];
    // d_in[3] = causal mask (unused)
    const float* Wq = (const float*)d_in[4];
    const float* Wk = (const float*)d_in[5];
    const float* Wv = (const float*)d_in[6];
    const float* Wo = (const float*)d_in[7];
    const float* bo = (const float*)d_in[8];
    float* out = (float*)d_out;

    float *gwt, *gq, *gk, *gv, *gc;
    cudaGetSymbolAddress((void**)&gwt, g_wt);
    cudaGetSymbolAddress((void**)&gq,  g_q);
    cudaGetSymbolAddress((void**)&gk,  g_k);
    cudaGetSymbolAddress((void**)&gv,  g_v);
    cudaGetSymbolAddress((void**)&gc,  g_c);
    float* gwt0 = gwt;
    float* gwt1 = gwt + (size_t)DD * DD;
    float* gwt2 = gwt + 2 * (size_t)DD * DD;

    cudaFuncSetAttribute(gemm_tf32, cudaFuncAttributeMaxDynamicSharedMemorySize, GEMM_SMEM);
    int asmem = 4 * 64 * AST * (int)sizeof(float);
    cudaFuncSetAttribute(attn_kernel, cudaFuncAttributeMaxDynamicSharedMemorySize, asmem);

    const dim3 tg(DKK / 32, DD / 32, HH);     // (2, 32, 16)
    const dim3 gg(DD / BN, NN / BM);          // (8, 64)

    transpose_w<<<tg, 256>>>(Wq, gwt0);
    transpose_w<<<tg, 256>>>(Wk, gwt1);
    transpose_w<<<tg, 256>>>(Wv, gwt2);
    gemm_tf32<<<gg, 256, GEMM_SMEM>>>(Q, gwt0, nullptr, gq);
    gemm_tf32<<<gg, 256, GEMM_SMEM>>>(K, gwt1, nullptr, gk);
    gemm_tf32<<<gg, 256, GEMM_SMEM>>>(V, gwt2, nullptr, gv);

    attn_kernel<<<dim3(SS/64, HH, BB), 256, asmem>>>(gq, gk, gv, gc);

    gemm_tf32<<<gg, 256, GEMM_SMEM>>>(gc, Wo, bo, out);
}